// round 16
// baseline (speedup 1.0000x reference)
#include <cuda_runtime.h>
#include <cuda_fp16.h>
#include <cstdint>

// Problem: B=16384, IN_DIM=1024, D=256, C=100
#define Bsz    16384
#define KDIM   1024
#define DDIM   256
#define CNUM   100
#define CPAD   112

#define BM 128
#define BK 64
#define NITER (KDIM / BK)     // 16
#define NT 1024               // 32 warps, 8 per SMSP

// strides: AST/BST/ZST in fp16 elems ((s/2)%32==4 -> conflict-free frags);
// XST in fp32 elems (XST%32==4); PSTF full-row P stride (264/2)%32==4.
#define AST 72
#define BST 72
#define ZST 264
#define PSTF 264
#define XST 68

#define A_SLOT_BYTES (BM * AST * 2)        // 18432, 2 slots
#define B_SLOT_BYTES (256 * BST * 2)       // 36864, 2 slots
#define X_SLOT_BYTES (BM * XST * 4)        // 34816, 3 slots
#define B_OFF (2 * A_SLOT_BYTES)           // 36864
#define X_OFF (B_OFF + 2 * B_SLOT_BYTES)   // 110592
#define DYN_BYTES (X_OFF + 3 * X_SLOT_BYTES)   // 215040

#define ZS_BYTES (BM * ZST * 2)            // 67584 (reuses mainloop smem)
#define PFULL_BYTES (CPAD * PSTF * 2)      // 59136

// Pre-converted fp16 operands (device globals: allocation-free)
__device__ __half g_wt[(size_t)DDIM * KDIM];  // W^T, [n][k]
__device__ __half g_ph[CPAD * DDIM];          // P padded, [c][k]
__device__ float  g_pn[CPAD];                 // |P_c|^2

// ---------------------------------------------------------------------------
__device__ __forceinline__ uint32_t smem_u32(const void* p) {
    uint32_t a;
    asm("{ .reg .u64 t; cvta.to.shared.u64 t, %1; cvt.u32.u64 %0, t; }"
        : "=r"(a) : "l"(p));
    return a;
}

#define CP_ASYNC16(dst, src) \
    asm volatile("cp.async.cg.shared.global [%0], [%1], 16;" \
                 :: "r"(dst), "l"(src) : "memory")
#define CP_COMMIT() asm volatile("cp.async.commit_group;" ::: "memory")
#define CP_WAIT3()  asm volatile("cp.async.wait_group 3;" ::: "memory")
#define CP_WAIT1()  asm volatile("cp.async.wait_group 1;" ::: "memory")
#define CP_WAIT0()  asm volatile("cp.async.wait_group 0;" ::: "memory")

#define MMA_F16(d, a, b) \
    asm volatile("mma.sync.aligned.m16n8k16.row.col.f32.f16.f16.f32 " \
        "{%0,%1,%2,%3}, {%4,%5,%6,%7}, {%8,%9}, {%0,%1,%2,%3};" \
        : "+f"((d)[0]), "+f"((d)[1]), "+f"((d)[2]), "+f"((d)[3]) \
        : "r"((a)[0]), "r"((a)[1]), "r"((a)[2]), "r"((a)[3]), \
          "r"((b)[0]), "r"((b)[1]))

#define LDMX4(r0, r1, r2, r3, addr) \
    asm volatile("ldmatrix.sync.aligned.m8n8.x4.shared.b16 {%0,%1,%2,%3}, [%4];" \
        : "=r"(r0), "=r"(r1), "=r"(r2), "=r"(r3) : "r"(addr))

// ---------------------------------------------------------------------------
// Pre-pass (small): W transpose->fp16, P pad->fp16 + |P|^2.
// ---------------------------------------------------------------------------
#define WBLKS 256
#define PBLKS 14
#define PREP_GRID (WBLKS + PBLKS)

__global__ void __launch_bounds__(256)
prep_kernel(const float* __restrict__ W,
            const float* __restrict__ P)
{
    const int b   = blockIdx.x;
    const int tid = threadIdx.x;

    if (b < WBLKS) {
        __shared__ float t[32][33];
        const int bx = (b & 7) * 32;    // n
        const int by = (b >> 3) * 32;   // k
        const int tx = tid & 31, ty = tid >> 5;
#pragma unroll
        for (int j = 0; j < 32; j += 8)
            t[ty + j][tx] = W[(size_t)(by + ty + j) * DDIM + bx + tx];
        __syncthreads();
#pragma unroll
        for (int j = 0; j < 32; j += 8)
            g_wt[(size_t)(bx + ty + j) * KDIM + by + tx] =
                __float2half_rn(t[tx][ty + j]);
    } else {
        const int c    = (b - WBLKS) * 8 + (tid >> 5);
        const int lane = tid & 31;
        float4 v0 = make_float4(0.f, 0.f, 0.f, 0.f), v1 = v0;
        if (c < CNUM) {
            const float4* p4 = reinterpret_cast<const float4*>(P + (size_t)c * DDIM);
            v0 = p4[lane];
            v1 = p4[lane + 32];
        }
        __half2 h0[2] = { __floats2half2_rn(v0.x, v0.y), __floats2half2_rn(v0.z, v0.w) };
        __half2 h1[2] = { __floats2half2_rn(v1.x, v1.y), __floats2half2_rn(v1.z, v1.w) };
        if (c < CPAD) {
            *reinterpret_cast<uint2*>(&g_ph[c * DDIM + lane * 4])       = *reinterpret_cast<uint2*>(h0);
            *reinterpret_cast<uint2*>(&g_ph[c * DDIM + 128 + lane * 4]) = *reinterpret_cast<uint2*>(h1);
        }
        float s = v0.x * v0.x + v0.y * v0.y + v0.z * v0.z + v0.w * v0.w
                + v1.x * v1.x + v1.y * v1.y + v1.z * v1.z + v1.w * v1.w;
#pragma unroll
        for (int o = 16; o > 0; o >>= 1) s += __shfl_xor_sync(0xffffffffu, s, o);
        if (lane == 0 && c < CPAD) g_pn[c] = s;
    }
}

// ---------------------------------------------------------------------------
// Fused kernel: 1024 thr / 32 warps, grid 128 (one wave, 1 CTA/SM).
// GEMM1 warp tile 32m x 32n  (warp_m = wid&3, warp_n = wid>>2).
// Mainloop schedule = R14 (proven). Tail = R15 (full-P, barrier-free MMA2).
// ---------------------------------------------------------------------------
__global__ void __launch_bounds__(NT, 1)
fused_kernel(const float* __restrict__ x,
             const float* __restrict__ bias,
             float* __restrict__ out)
{
    extern __shared__ __align__(16) unsigned char dyn[];
    __shared__ float s_bias[DDIM];
    __shared__ float srow[BM];
    __shared__ float s_pn[CPAD];

    const int tid  = threadIdx.x;
    const int wid  = tid >> 5;
    const int lane = tid & 31;
    const int lq = lane >> 2;
    const int lr = lane & 3;
    const int mBase = blockIdx.x * BM;

    const int warp_m = wid & 3;    // 0..3 : 32 rows
    const int warp_n = wid >> 2;   // 0..7 : 32 cols

    if (tid < DDIM) s_bias[tid] = bias[tid];
    if (tid < BM)   srow[tid] = 0.0f;
    if (tid < CPAD) s_pn[tid] = g_pn[tid];

    const uint32_t dynb = smem_u32(dyn);

    // ldmatrix lane byte-offsets (within A/B slot)
    const uint32_t aLane = (uint32_t)(warp_m * 32 + (lane & 15)) * (AST * 2)
                         + (uint32_t)((lane >> 4) * 16);
    const uint32_t bLane = (uint32_t)(warp_n * 32 + (lane & 7)
                                      + ((lane & 16) ? 8 : 0)) * (BST * 2)
                         + (uint32_t)((lane & 8) ? 16 : 0);

    // ---- X stage loader: 2048 chunks of 16B, 2/thread ----
    auto cpX = [&](int kIter, int slot) {
        const int k0 = kIter * BK;
        const uint32_t xB = dynb + X_OFF + slot * X_SLOT_BYTES;
#pragma unroll
        for (int i = 0; i < 2; i++) {
            const int c = tid + (i << 10);
            const int row = c >> 4, seg = c & 15;
            CP_ASYNC16(xB + row * (XST * 4) + seg * 16,
                       x + (size_t)(mBase + row) * KDIM + k0 + seg * 4);
        }
    };

    // ---- convert: x-stage slot (fp32) -> A slot (fp16); 8 floats/thread --
    const int arow = tid & 127;
    const int aq   = tid >> 7;     // 0..7
    auto convert = [&](int xslot, int aslot) {
        const float4* s = reinterpret_cast<const float4*>(
            dyn + X_OFF + xslot * X_SLOT_BYTES) + (arow * XST + aq * 8) / 4;
        float4 v0 = s[0], v1 = s[1];
        __half2 h0 = __floats2half2_rn(v0.x, v0.y);
        __half2 h1 = __floats2half2_rn(v0.z, v0.w);
        __half2 h2 = __floats2half2_rn(v1.x, v1.y);
        __half2 h3 = __floats2half2_rn(v1.z, v1.w);
        uint4* d = reinterpret_cast<uint4*>(
            reinterpret_cast<uint32_t*>(dyn + aslot * A_SLOT_BYTES)
            + arow * (AST / 2) + aq * 4);
        d[0] = make_uint4(*reinterpret_cast<uint32_t*>(&h0),
                          *reinterpret_cast<uint32_t*>(&h1),
                          *reinterpret_cast<uint32_t*>(&h2),
                          *reinterpret_cast<uint32_t*>(&h3));
    };

    auto loadB = [&](int kIter, int slot) {
        const int k0 = kIter * BK;
        const uint32_t bB = dynb + B_OFF + slot * B_SLOT_BYTES;
#pragma unroll
        for (int i = 0; i < 2; i++) {
            const int c = tid + (i << 10);
            const int row = c >> 3, seg = c & 7;
            CP_ASYNC16(bB + row * (BST * 2) + seg * 16,
                       g_wt + (size_t)row * KDIM + k0 + seg * 8);
        }
    };

    // prologue: groups X0, B0, X1, X2
    cpX(0, 0);   CP_COMMIT();
    loadB(0, 0); CP_COMMIT();
    cpX(1, 1);   CP_COMMIT();
    cpX(2, 2);   CP_COMMIT();
    CP_WAIT3();            // X0 complete
    __syncthreads();
    convert(0, 0);         // A slot 0 ready after next sync

    float acc[2][4][4];
#pragma unroll
    for (int i = 0; i < 2; i++)
#pragma unroll
        for (int j = 0; j < 4; j++)
#pragma unroll
            for (int r = 0; r < 4; r++) acc[i][j][r] = 0.0f;

    for (int it = 0; it < NITER; ++it) {
        if (it <= NITER - 3) { CP_WAIT1(); } else { CP_WAIT0(); }
        __syncthreads();   // retires MMA(it-1) frag reads & convert writes

        if (it + 1 < NITER) { loadB(it + 1, (it + 1) & 1); CP_COMMIT(); }
        if (it + 3 < NITER) { cpX(it + 3, (it + 3) % 3);   CP_COMMIT(); }

        const uint32_t aSlot = dynb + (it & 1) * A_SLOT_BYTES + aLane;
        const uint32_t bSlot = dynb + B_OFF + (it & 1) * B_SLOT_BYTES + bLane;

#pragma unroll
        for (int kk = 0; kk < 4; kk++) {
            uint32_t au[2][4], bu[4][2];
#pragma unroll
            for (int mi = 0; mi < 2; mi++)
                LDMX4(au[mi][0], au[mi][1], au[mi][2], au[mi][3],
                      aSlot + mi * 16 * (AST * 2) + kk * 32);
#pragma unroll
            for (int g = 0; g < 2; g++)
                LDMX4(bu[2 * g][0], bu[2 * g][1], bu[2 * g + 1][0], bu[2 * g + 1][1],
                      bSlot + g * 16 * (BST * 2) + kk * 32);
#pragma unroll
            for (int mi = 0; mi < 2; mi++)
#pragma unroll
                for (int nj = 0; nj < 4; nj++)
                    MMA_F16(acc[mi][nj], au[mi], bu[nj]);
        }

        if (it + 1 < NITER) convert((it + 1) % 3, (it + 1) & 1);
    }
    __syncthreads();   // stage buffers dead; smem reused below

    // ======================= epilogue A ====================================
    __half2* Zs2 = reinterpret_cast<__half2*>(dyn);
    const uint32_t pbu = dynb + ZS_BYTES;          // full P, 59136 B

    // Issue FULL P load now (one commit group); 3584 chunks, <=4/thread.
    {
#pragma unroll
        for (int i = 0; i < 4; i++) {
            const int c = tid + (i << 10);
            if (c < CPAD * 32) {
                const int row = c >> 5, seg = c & 31;
                CP_ASYNC16(pbu + row * (PSTF * 2) + seg * 16,
                           g_ph + row * DDIM + seg * 8);
            }
        }
        CP_COMMIT();
    }

    {
        float rsum[2][2];
#pragma unroll
        for (int mi = 0; mi < 2; mi++) { rsum[mi][0] = 0.f; rsum[mi][1] = 0.f; }

#pragma unroll
        for (int mi = 0; mi < 2; mi++) {
            const int rowA = warp_m * 32 + mi * 16 + lq;
#pragma unroll
            for (int nj = 0; nj < 4; nj++) {
                const int n0 = warp_n * 32 + nj * 8 + 2 * lr;
                float v0 = acc[mi][nj][0] + s_bias[n0];
                float v1 = acc[mi][nj][1] + s_bias[n0 + 1];
                float v2 = acc[mi][nj][2] + s_bias[n0];
                float v3 = acc[mi][nj][3] + s_bias[n0 + 1];
                rsum[mi][0] += v0 * v0 + v1 * v1;
                rsum[mi][1] += v2 * v2 + v3 * v3;
                Zs2[rowA * (ZST / 2) + (n0 >> 1)] = __floats2half2_rn(v0, v1);
                Zs2[(rowA + 8) * (ZST / 2) + (n0 >> 1)] = __floats2half2_rn(v2, v3);
            }
        }
#pragma unroll
        for (int mi = 0; mi < 2; mi++) {
#pragma unroll
            for (int h = 0; h < 2; h++) {
                float s = rsum[mi][h];
                s += __shfl_xor_sync(0xffffffffu, s, 1);
                s += __shfl_xor_sync(0xffffffffu, s, 2);
                if (lr == 0)
                    atomicAdd(&srow[warp_m * 32 + mi * 16 + lq + 8 * h], s);
            }
        }
    }

    // One wait + one sync orders: P resident, Zs written, srow atomics done.
    CP_WAIT0();
    __syncthreads();

    // ======================= phase 2: MMA2 (barrier-free) ==================
    // 32 warps: warp_m2 = wid>>2 (0..7, 16 rows), warp_n2 = wid&3.
    // n8-tile t = warp_n2 + 4*j, j=0..3, active while t < 14.
    const int warp_m2 = wid >> 2;
    const int warp_n2 = wid & 3;

    float acc2[4][4];
#pragma unroll
    for (int j = 0; j < 4; j++)
#pragma unroll
        for (int r = 0; r < 4; r++) acc2[j][r] = 0.0f;

    const uint32_t* Zs32 = reinterpret_cast<const uint32_t*>(dyn);
    const uint32_t* zP = Zs32 + (warp_m2 * 16 + lq) * (ZST / 2) + lr;
    const uint32_t* Ps = reinterpret_cast<const uint32_t*>(dyn + ZS_BYTES);
    const uint32_t* pP = Ps + (warp_n2 * 8 + lq) * (PSTF / 2) + lr;

#pragma unroll
    for (int kk = 0; kk < 16; kk++) {
        uint32_t au[4], bu[4][2];
        const uint32_t* zp = zP + kk * 8;
        au[0] = zp[0];
        au[1] = zp[8 * (ZST / 2)];
        au[2] = zp[4];
        au[3] = zp[8 * (ZST / 2) + 4];
#pragma unroll
        for (int j = 0; j < 4; j++) {
            const int t = warp_n2 + 4 * j;
            if (t < 14) {
                const uint32_t* p = pP + j * 32 * (PSTF / 2) + kk * 8;
                bu[j][0] = p[0];
                bu[j][1] = p[4];
            }
        }
#pragma unroll
        for (int j = 0; j < 4; j++)
            if (warp_n2 + 4 * j < 14)
                MMA_F16(acc2[j], au, bu[j]);
    }

    // ======================= epilogue B ====================================
    const float inv = 1.0f / (float)DDIM;
    const int rowA = warp_m2 * 16 + lq;
    const int rowB = rowA + 8;
    const float rsA = srow[rowA];
    const float rsB = srow[rowB];
#pragma unroll
    for (int j = 0; j < 4; j++) {
        const int t = warp_n2 + 4 * j;
        if (t >= 14) continue;
        const int c0 = t * 8 + 2 * lr;
        const float pn0 = s_pn[c0];
        const float pn1 = s_pn[c0 + 1];
        if (c0 < CNUM)
            out[(size_t)(mBase + rowA) * CNUM + c0] =
                (2.0f * acc2[j][0] - rsA - pn0) * inv;
        if (c0 + 1 < CNUM)
            out[(size_t)(mBase + rowA) * CNUM + c0 + 1] =
                (2.0f * acc2[j][1] - rsA - pn1) * inv;
        if (c0 < CNUM)
            out[(size_t)(mBase + rowB) * CNUM + c0] =
                (2.0f * acc2[j][2] - rsB - pn0) * inv;
        if (c0 + 1 < CNUM)
            out[(size_t)(mBase + rowB) * CNUM + c0 + 1] =
                (2.0f * acc2[j][3] - rsB - pn1) * inv;
    }
}

// ---------------------------------------------------------------------------
extern "C" void kernel_launch(void* const* d_in, const int* in_sizes, int n_in,
                              void* d_out, int out_size)
{
    const float* x  = (const float*)d_in[0];
    const float* W  = (const float*)d_in[1];
    const float* b  = (const float*)d_in[2];
    const float* P  = (const float*)d_in[3];
    float* out = (float*)d_out;

    cudaFuncSetAttribute(fused_kernel,
                         cudaFuncAttributeMaxDynamicSharedMemorySize, DYN_BYTES);

    prep_kernel<<<PREP_GRID, 256>>>(W, P);
    fused_kernel<<<Bsz / BM, NT, DYN_BYTES>>>(x, b, out);
}

// round 17
// speedup vs baseline: 1.0949x; 1.0949x over previous
#include <cuda_runtime.h>
#include <cuda_fp16.h>
#include <cstdint>

// Problem: B=16384, IN_DIM=1024, D=256, C=100
#define Bsz    16384
#define KDIM   1024
#define DDIM   256
#define CNUM   100
#define CPAD   112

#define BM 128
#define BK 64
#define NITER (KDIM / BK)     // 16
#define NT 512

// strides: AST/BST/ZST in fp16 elems ((s/2)%32==4 -> conflict-free frags);
// XST in fp32 elems (XST%32==4); PSTF full-row P stride (264/2)%32==4.
#define AST 72
#define BST 72
#define ZST 264
#define PSTF 264
#define XST 68

#define A_SLOT_BYTES (BM * AST * 2)        // 18432, 2 slots
#define B_SLOT_BYTES (256 * BST * 2)       // 36864, 2 slots
#define X_SLOT_BYTES (BM * XST * 4)        // 34816, 3 slots
#define B_OFF (2 * A_SLOT_BYTES)           // 36864
#define X_OFF (B_OFF + 2 * B_SLOT_BYTES)   // 110592
#define DYN_BYTES (X_OFF + 3 * X_SLOT_BYTES)   // 215040

#define ZS_BYTES (BM * ZST * 2)            // 67584 (reuses mainloop smem)
#define PFULL_BYTES (CPAD * PSTF * 2)      // 59136

// Pre-converted fp16 operands (device globals: allocation-free)
__device__ __half g_wt[(size_t)DDIM * KDIM];  // W^T, [n][k]
__device__ __half g_ph[CPAD * DDIM];          // P padded, [c][k]
__device__ float  g_pn[CPAD];                 // |P_c|^2

// ---------------------------------------------------------------------------
__device__ __forceinline__ uint32_t smem_u32(const void* p) {
    uint32_t a;
    asm("{ .reg .u64 t; cvta.to.shared.u64 t, %1; cvt.u32.u64 %0, t; }"
        : "=r"(a) : "l"(p));
    return a;
}

#define CP_ASYNC16(dst, src) \
    asm volatile("cp.async.cg.shared.global [%0], [%1], 16;" \
                 :: "r"(dst), "l"(src) : "memory")
#define CP_COMMIT() asm volatile("cp.async.commit_group;" ::: "memory")
#define CP_WAIT3()  asm volatile("cp.async.wait_group 3;" ::: "memory")
#define CP_WAIT1()  asm volatile("cp.async.wait_group 1;" ::: "memory")
#define CP_WAIT0()  asm volatile("cp.async.wait_group 0;" ::: "memory")

#define MMA_F16(d, a, b) \
    asm volatile("mma.sync.aligned.m16n8k16.row.col.f32.f16.f16.f32 " \
        "{%0,%1,%2,%3}, {%4,%5,%6,%7}, {%8,%9}, {%0,%1,%2,%3};" \
        : "+f"((d)[0]), "+f"((d)[1]), "+f"((d)[2]), "+f"((d)[3]) \
        : "r"((a)[0]), "r"((a)[1]), "r"((a)[2]), "r"((a)[3]), \
          "r"((b)[0]), "r"((b)[1]))

#define LDMX4(r0, r1, r2, r3, addr) \
    asm volatile("ldmatrix.sync.aligned.m8n8.x4.shared.b16 {%0,%1,%2,%3}, [%4];" \
        : "=r"(r0), "=r"(r1), "=r"(r2), "=r"(r3) : "r"(addr))

// ---------------------------------------------------------------------------
// Pre-pass (small): W transpose->fp16, P pad->fp16 + |P|^2.
// ---------------------------------------------------------------------------
#define WBLKS 256
#define PBLKS 14
#define PREP_GRID (WBLKS + PBLKS)

__global__ void __launch_bounds__(256)
prep_kernel(const float* __restrict__ W,
            const float* __restrict__ P)
{
    const int b   = blockIdx.x;
    const int tid = threadIdx.x;

    if (b < WBLKS) {
        __shared__ float t[32][33];
        const int bx = (b & 7) * 32;    // n
        const int by = (b >> 3) * 32;   // k
        const int tx = tid & 31, ty = tid >> 5;
#pragma unroll
        for (int j = 0; j < 32; j += 8)
            t[ty + j][tx] = W[(size_t)(by + ty + j) * DDIM + bx + tx];
        __syncthreads();
#pragma unroll
        for (int j = 0; j < 32; j += 8)
            g_wt[(size_t)(bx + ty + j) * KDIM + by + tx] =
                __float2half_rn(t[tx][ty + j]);
    } else {
        const int c    = (b - WBLKS) * 8 + (tid >> 5);
        const int lane = tid & 31;
        float4 v0 = make_float4(0.f, 0.f, 0.f, 0.f), v1 = v0;
        if (c < CNUM) {
            const float4* p4 = reinterpret_cast<const float4*>(P + (size_t)c * DDIM);
            v0 = p4[lane];
            v1 = p4[lane + 32];
        }
        __half2 h0[2] = { __floats2half2_rn(v0.x, v0.y), __floats2half2_rn(v0.z, v0.w) };
        __half2 h1[2] = { __floats2half2_rn(v1.x, v1.y), __floats2half2_rn(v1.z, v1.w) };
        if (c < CPAD) {
            *reinterpret_cast<uint2*>(&g_ph[c * DDIM + lane * 4])       = *reinterpret_cast<uint2*>(h0);
            *reinterpret_cast<uint2*>(&g_ph[c * DDIM + 128 + lane * 4]) = *reinterpret_cast<uint2*>(h1);
        }
        float s = v0.x * v0.x + v0.y * v0.y + v0.z * v0.z + v0.w * v0.w
                + v1.x * v1.x + v1.y * v1.y + v1.z * v1.z + v1.w * v1.w;
#pragma unroll
        for (int o = 16; o > 0; o >>= 1) s += __shfl_xor_sync(0xffffffffu, s, o);
        if (lane == 0 && c < CPAD) g_pn[c] = s;
    }
}

// ---------------------------------------------------------------------------
// Fused kernel: 512 thr / 16 warps, grid 128 (one wave, 1 CTA/SM).
// R15 structure; cp.async issues moved AFTER the kk=0 MMA block so the
// post-barrier critical path starts with LDSM/MMA, not an LSU burst.
// ---------------------------------------------------------------------------
__global__ void __launch_bounds__(NT, 1)
fused_kernel(const float* __restrict__ x,
             const float* __restrict__ bias,
             float* __restrict__ out)
{
    extern __shared__ __align__(16) unsigned char dyn[];
    __shared__ float s_bias[DDIM];
    __shared__ float srow[BM];
    __shared__ float s_pn[CPAD];

    const int tid  = threadIdx.x;
    const int wid  = tid >> 5;
    const int lane = tid & 31;
    const int lq = lane >> 2;
    const int lr = lane & 3;
    const int mBase = blockIdx.x * BM;

    const int warp_m = wid & 1;    // 0..1 : 64 rows
    const int warp_n = wid >> 1;   // 0..7 : 32 cols

    if (tid < DDIM) s_bias[tid] = bias[tid];
    if (tid < BM)   srow[tid] = 0.0f;
    if (tid < CPAD) s_pn[tid] = g_pn[tid];

    const uint32_t dynb = smem_u32(dyn);

    // ldmatrix lane byte-offsets (within A/B slot)
    const uint32_t aLane = (uint32_t)(warp_m * 64 + (lane & 15)) * (AST * 2)
                         + (uint32_t)((lane >> 4) * 16);
    const uint32_t bLane = (uint32_t)(warp_n * 32 + (lane & 7)
                                      + ((lane & 16) ? 8 : 0)) * (BST * 2)
                         + (uint32_t)((lane & 8) ? 16 : 0);

    // ---- X stage loader: 2048 chunks of 16B, 4/thread ----
    auto cpX = [&](int kIter, int slot) {
        const int k0 = kIter * BK;
        const uint32_t xB = dynb + X_OFF + slot * X_SLOT_BYTES;
#pragma unroll
        for (int i = 0; i < 4; i++) {
            const int c = tid + (i << 9);
            const int row = c >> 4, seg = c & 15;
            CP_ASYNC16(xB + row * (XST * 4) + seg * 16,
                       x + (size_t)(mBase + row) * KDIM + k0 + seg * 4);
        }
    };

    // ---- convert: x-stage slot (fp32) -> A slot (fp16) ----
    const int arow = tid & 127;
    const int aq   = tid >> 7;     // 0..3
    auto convert = [&](int xslot, int aslot) {
        const float4* s = reinterpret_cast<const float4*>(
            dyn + X_OFF + xslot * X_SLOT_BYTES) + (arow * XST + aq * 16) / 4;
        uint32_t h[8];
#pragma unroll
        for (int j = 0; j < 4; j++) {
            float4 v = s[j];
            __half2 h0 = __floats2half2_rn(v.x, v.y);
            __half2 h1 = __floats2half2_rn(v.z, v.w);
            h[2 * j]     = *reinterpret_cast<uint32_t*>(&h0);
            h[2 * j + 1] = *reinterpret_cast<uint32_t*>(&h1);
        }
        uint4* d = reinterpret_cast<uint4*>(
            reinterpret_cast<uint32_t*>(dyn + aslot * A_SLOT_BYTES)
            + arow * (AST / 2) + aq * 8);
        d[0] = make_uint4(h[0], h[1], h[2], h[3]);
        d[1] = make_uint4(h[4], h[5], h[6], h[7]);
    };

    auto loadB = [&](int kIter, int slot) {
        const int k0 = kIter * BK;
        const uint32_t bB = dynb + B_OFF + slot * B_SLOT_BYTES;
#pragma unroll
        for (int i = 0; i < 4; i++) {
            const int c = tid + (i << 9);
            const int row = c >> 3, seg = c & 7;
            CP_ASYNC16(bB + row * (BST * 2) + seg * 16,
                       g_wt + (size_t)row * KDIM + k0 + seg * 8);
        }
    };

    // prologue: groups X0, B0, X1, X2  (4 groups)
    cpX(0, 0);   CP_COMMIT();
    loadB(0, 0); CP_COMMIT();
    cpX(1, 1);   CP_COMMIT();
    cpX(2, 2);   CP_COMMIT();
    CP_WAIT3();            // X0 complete
    __syncthreads();
    convert(0, 0);         // A slot 0 ready after next sync

    float acc[4][4][4];
#pragma unroll
    for (int i = 0; i < 4; i++)
#pragma unroll
        for (int j = 0; j < 4; j++)
#pragma unroll
            for (int r = 0; r < 4; r++) acc[i][j][r] = 0.0f;

    for (int it = 0; it < NITER; ++it) {
        if (it <= NITER - 3) { CP_WAIT1(); } else { CP_WAIT0(); }
        __syncthreads();   // retires MMA(it-1) frag reads & convert writes

        const uint32_t aSlot = dynb + (it & 1) * A_SLOT_BYTES + aLane;
        const uint32_t bSlot = dynb + B_OFF + (it & 1) * B_SLOT_BYTES + bLane;

#pragma unroll
        for (int kk = 0; kk < 4; kk++) {
            uint32_t au[4][4], bu[4][2];
#pragma unroll
            for (int mi = 0; mi < 4; mi++)
                LDMX4(au[mi][0], au[mi][1], au[mi][2], au[mi][3],
                      aSlot + mi * 16 * (AST * 2) + kk * 32);
#pragma unroll
            for (int g = 0; g < 2; g++)
                LDMX4(bu[2 * g][0], bu[2 * g][1], bu[2 * g + 1][0], bu[2 * g + 1][1],
                      bSlot + g * 16 * (BST * 2) + kk * 32);
#pragma unroll
            for (int mi = 0; mi < 4; mi++)
#pragma unroll
                for (int nj = 0; nj < 4; nj++)
                    MMA_F16(acc[mi][nj], au[mi], bu[nj]);

            // Issue next-stage loads after kk=0 (off the post-barrier
            // critical path; still before the waits that consume them).
            if (kk == 0) {
                if (it + 1 < NITER) { loadB(it + 1, (it + 1) & 1); CP_COMMIT(); }
                if (it + 3 < NITER) { cpX(it + 3, (it + 3) % 3);   CP_COMMIT(); }
            }
        }

        // convert AFTER the MMAs: off the iteration-top critical path.
        if (it + 1 < NITER) convert((it + 1) % 3, (it + 1) & 1);
    }
    __syncthreads();   // stage buffers dead; smem reused below

    // ======================= epilogue A ====================================
    __half2* Zs2 = reinterpret_cast<__half2*>(dyn);
    const uint32_t pbu = dynb + ZS_BYTES;          // full P, 59136 B

    // Issue FULL P load now (one commit group); overlaps with epilogue A.
    {
#pragma unroll
        for (int i = 0; i < 7; i++) {
            const int c = tid + (i << 9);
            const int row = c >> 5, seg = c & 31;
            CP_ASYNC16(pbu + row * (PSTF * 2) + seg * 16,
                       g_ph + row * DDIM + seg * 8);
        }
        CP_COMMIT();
    }

    {
        float rsum[4][2];
#pragma unroll
        for (int mi = 0; mi < 4; mi++) { rsum[mi][0] = 0.f; rsum[mi][1] = 0.f; }

#pragma unroll
        for (int mi = 0; mi < 4; mi++) {
            const int rowA = warp_m * 64 + mi * 16 + lq;
#pragma unroll
            for (int nj = 0; nj < 4; nj++) {
                const int n0 = warp_n * 32 + nj * 8 + 2 * lr;
                float v0 = acc[mi][nj][0] + s_bias[n0];
                float v1 = acc[mi][nj][1] + s_bias[n0 + 1];
                float v2 = acc[mi][nj][2] + s_bias[n0];
                float v3 = acc[mi][nj][3] + s_bias[n0 + 1];
                rsum[mi][0] += v0 * v0 + v1 * v1;
                rsum[mi][1] += v2 * v2 + v3 * v3;
                Zs2[rowA * (ZST / 2) + (n0 >> 1)] = __floats2half2_rn(v0, v1);
                Zs2[(rowA + 8) * (ZST / 2) + (n0 >> 1)] = __floats2half2_rn(v2, v3);
            }
        }
#pragma unroll
        for (int mi = 0; mi < 4; mi++) {
#pragma unroll
            for (int h = 0; h < 2; h++) {
                float s = rsum[mi][h];
                s += __shfl_xor_sync(0xffffffffu, s, 1);
                s += __shfl_xor_sync(0xffffffffu, s, 2);
                if (lr == 0)
                    atomicAdd(&srow[warp_m * 64 + mi * 16 + lq + 8 * h], s);
            }
        }
    }

    // One wait + one sync orders: P resident, Zs written, srow atomics done.
    CP_WAIT0();
    __syncthreads();

    // ======================= phase 2: MMA2 (barrier-free) ==================
    const int warp_m2 = wid >> 1;   // 0..7 : 16 rows
    const int warp_n2 = wid & 1;    // 0..1 : 56 cols

    float acc2[7][4];
#pragma unroll
    for (int j = 0; j < 7; j++)
#pragma unroll
        for (int r = 0; r < 4; r++) acc2[j][r] = 0.0f;

    const uint32_t* Zs32 = reinterpret_cast<const uint32_t*>(dyn);
    const uint32_t* zP = Zs32 + (warp_m2 * 16 + lq) * (ZST / 2) + lr;
    const uint32_t* Ps = reinterpret_cast<const uint32_t*>(dyn + ZS_BYTES);
    const uint32_t* pP = Ps + (warp_n2 * 56 + lq) * (PSTF / 2) + lr;

#pragma unroll
    for (int kk = 0; kk < 16; kk++) {
        uint32_t au[4], bu[7][2];
        const uint32_t* zp = zP + kk * 8;
        au[0] = zp[0];
        au[1] = zp[8 * (ZST / 2)];
        au[2] = zp[4];
        au[3] = zp[8 * (ZST / 2) + 4];
#pragma unroll
        for (int nj = 0; nj < 7; nj++) {
            const uint32_t* p = pP + nj * 8 * (PSTF / 2) + kk * 8;
            bu[nj][0] = p[0];
            bu[nj][1] = p[4];
        }
#pragma unroll
        for (int nj = 0; nj < 7; nj++)
            MMA_F16(acc2[nj], au, bu[nj]);
    }

    // ======================= epilogue B ====================================
    const float inv = 1.0f / (float)DDIM;
    const int rowA = warp_m2 * 16 + lq;
    const int rowB = rowA + 8;
    const float rsA = srow[rowA];
    const float rsB = srow[rowB];
#pragma unroll
    for (int nj = 0; nj < 7; nj++) {
        const int c0 = warp_n2 * 56 + nj * 8 + 2 * lr;
        const float pn0 = s_pn[c0];
        const float pn1 = s_pn[c0 + 1];
        if (c0 < CNUM)
            out[(size_t)(mBase + rowA) * CNUM + c0] =
                (2.0f * acc2[nj][0] - rsA - pn0) * inv;
        if (c0 + 1 < CNUM)
            out[(size_t)(mBase + rowA) * CNUM + c0 + 1] =
                (2.0f * acc2[nj][1] - rsA - pn1) * inv;
        if (c0 < CNUM)
            out[(size_t)(mBase + rowB) * CNUM + c0] =
                (2.0f * acc2[nj][2] - rsB - pn0) * inv;
        if (c0 + 1 < CNUM)
            out[(size_t)(mBase + rowB) * CNUM + c0 + 1] =
                (2.0f * acc2[nj][3] - rsB - pn1) * inv;
    }
}

// ---------------------------------------------------------------------------
extern "C" void kernel_launch(void* const* d_in, const int* in_sizes, int n_in,
                              void* d_out, int out_size)
{
    const float* x  = (const float*)d_in[0];
    const float* W  = (const float*)d_in[1];
    const float* b  = (const float*)d_in[2];
    const float* P  = (const float*)d_in[3];
    float* out = (float*)d_out;

    cudaFuncSetAttribute(fused_kernel,
                         cudaFuncAttributeMaxDynamicSharedMemorySize, DYN_BYTES);

    prep_kernel<<<PREP_GRID, 256>>>(W, P);
    fused_kernel<<<Bsz / BM, NT, DYN_BYTES>>>(x, b, out);
}